// round 5
// baseline (speedup 1.0000x reference)
#include <cuda_runtime.h>

// ComplexScaling: separable bilinear grid_sample, s = 1 + theta[0],
// align_corners=False, zeros padding. input [32,1024,1024,2] fp32 NHWC.
//
// Each thread owns two float4s (32B, MLP=2). s == 1.0f -> exact identity in
// fp32 -> pure streaming copy (L2::256B-hinted loads, evict-first stores).
// Otherwise generic 4-corner bilinear (verified R1/R2/R4).

#define HH 1024
#define WW 1024
#define NPIX (32 * HH * WW)   // total float2 pixels = 33,554,432

__device__ __forceinline__ float4 ldg_256hint(const float4* p)
{
    float4 v;
    asm volatile("ld.global.nc.L2::256B.v4.f32 {%0,%1,%2,%3}, [%4];"
                 : "=f"(v.x), "=f"(v.y), "=f"(v.z), "=f"(v.w)
                 : "l"(p));
    return v;
}

__device__ __forceinline__ void stg_cs(float4* p, float4 v)
{
    asm volatile("st.global.cs.v4.f32 [%0], {%1,%2,%3,%4};"
                 :: "l"(p), "f"(v.x), "f"(v.y), "f"(v.z), "f"(v.w)
                 : "memory");
}

__device__ __forceinline__ float4 bilinear_pair(const float2* __restrict__ img,
                                                int j0, float s,
                                                float mwy0, float mwy1,
                                                int cy0, int cy1)
{
    const int j1 = j0 + 1;
    const float xn0 = (2.0f * (float)j0 + 1.0f) * (1.0f / (float)WW) - 1.0f;
    const float xn1 = (2.0f * (float)j1 + 1.0f) * (1.0f / (float)WW) - 1.0f;
    const float ixa = ((s * xn0 + 1.0f) * (float)WW - 1.0f) * 0.5f;
    const float ixb = ((s * xn1 + 1.0f) * (float)WW - 1.0f) * 0.5f;
    const float fxa0 = floorf(ixa);
    const float fxb0 = floorf(ixb);
    const float wxa1 = ixa - fxa0;
    const float wxb1 = ixb - fxb0;
    const float wxa0 = 1.0f - wxa1;
    const float wxb0 = 1.0f - wxb1;
    const int xa0 = (int)fxa0;
    const int xb0 = (int)fxb0;
    const int xa1 = xa0 + 1;
    const int xb1 = xb0 + 1;

    const float mwxa0 = (xa0 >= 0 && xa0 < WW) ? wxa0 : 0.0f;
    const float mwxa1 = (xa1 >= 0 && xa1 < WW) ? wxa1 : 0.0f;
    const float mwxb0 = (xb0 >= 0 && xb0 < WW) ? wxb0 : 0.0f;
    const float mwxb1 = (xb1 >= 0 && xb1 < WW) ? wxb1 : 0.0f;
    const int cxa0 = min(max(xa0, 0), WW - 1);
    const int cxa1 = min(max(xa1, 0), WW - 1);
    const int cxb0 = min(max(xb0, 0), WW - 1);
    const int cxb1 = min(max(xb1, 0), WW - 1);

    const float2* r0 = img + (size_t)cy0 * WW;
    const float2* r1 = img + (size_t)cy1 * WW;

    const float2 a00 = __ldg(r0 + cxa0);
    const float2 a01 = __ldg(r0 + cxa1);
    const float2 a10 = __ldg(r1 + cxa0);
    const float2 a11 = __ldg(r1 + cxa1);
    const float2 b00 = __ldg(r0 + cxb0);
    const float2 b01 = __ldg(r0 + cxb1);
    const float2 b10 = __ldg(r1 + cxb0);
    const float2 b11 = __ldg(r1 + cxb1);

    float4 res;
    {
        const float r0x = mwxa0 * a00.x + mwxa1 * a01.x;
        const float r0y = mwxa0 * a00.y + mwxa1 * a01.y;
        const float r1x = mwxa0 * a10.x + mwxa1 * a11.x;
        const float r1y = mwxa0 * a10.y + mwxa1 * a11.y;
        res.x = mwy0 * r0x + mwy1 * r1x;
        res.y = mwy0 * r0y + mwy1 * r1y;
    }
    {
        const float r0x = mwxb0 * b00.x + mwxb1 * b01.x;
        const float r0y = mwxb0 * b00.y + mwxb1 * b01.y;
        const float r1x = mwxb0 * b10.x + mwxb1 * b11.x;
        const float r1y = mwxb0 * b10.y + mwxb1 * b11.y;
        res.z = mwy0 * r0x + mwy1 * r1x;
        res.w = mwy0 * r0y + mwy1 * r1y;
    }
    return res;
}

__global__ __launch_bounds__(256)
void complex_scaling_kernel(const float2* __restrict__ in,
                            const float* __restrict__ theta,
                            float2* __restrict__ out)
{
    const int t = blockIdx.x * blockDim.x + threadIdx.x;   // 32B chunk index
    const float s = 1.0f + __ldg(theta);

    if (s == 1.0f) {
        // ---- identity: streaming copy, 2x16B per thread (MLP=2) ----
        const float4* src = reinterpret_cast<const float4*>(in) + (size_t)t * 2;
        float4* dst       = reinterpret_cast<float4*>(out) + (size_t)t * 2;
        const float4 v0 = ldg_256hint(src + 0);
        const float4 v1 = ldg_256hint(src + 1);
        stg_cs(dst + 0, v0);
        stg_cs(dst + 1, v1);
        return;
    }

    // ---- generic bilinear path (4 pixels per thread) ----
    const int p   = t * 4;                 // first pixel index
    const int n   = p >> 20;               // / (HH*WW)
    const int rem = p & (HH * WW - 1);
    const int i   = rem >> 10;             // row
    const int j0  = rem & (WW - 1);        // first column (multiple of 4)

    const float yn  = (2.0f * (float)i + 1.0f) * (1.0f / (float)HH) - 1.0f;
    const float iy  = ((s * yn + 1.0f) * (float)HH - 1.0f) * 0.5f;
    const float fy0 = floorf(iy);
    const float wy1 = iy - fy0;
    const float wy0 = 1.0f - wy1;
    const int y0 = (int)fy0;
    const int y1 = y0 + 1;
    const float mwy0 = (y0 >= 0 && y0 < HH) ? wy0 : 0.0f;
    const float mwy1 = (y1 >= 0 && y1 < HH) ? wy1 : 0.0f;
    const int cy0 = min(max(y0, 0), HH - 1);
    const int cy1 = min(max(y1, 0), HH - 1);

    const float2* img = in + (size_t)n * (HH * WW);
    float4* dst = reinterpret_cast<float4*>(out) + (size_t)t * 2;

    const float4 r0 = bilinear_pair(img, j0,     s, mwy0, mwy1, cy0, cy1);
    const float4 r1 = bilinear_pair(img, j0 + 2, s, mwy0, mwy1, cy0, cy1);
    dst[0] = r0;
    dst[1] = r1;
}

extern "C" void kernel_launch(void* const* d_in, const int* in_sizes, int n_in,
                              void* d_out, int out_size)
{
    const float2* in   = (const float2*)d_in[0];   // [32,1024,1024,2] fp32
    const float* theta = (const float*)d_in[1];    // [1] fp32
    float2* out        = (float2*)d_out;

    const int threads = NPIX / 4;                  // 32B per thread
    complex_scaling_kernel<<<threads / 256, 256>>>(in, theta, out);
}